// round 13
// baseline (speedup 1.0000x reference)
#include <cuda_runtime.h>
#include <math.h>

#define H 1024
#define VOCAB 50257
#define NB 148                  // persistent LSTM kernel: one block per SM
#define NT 1024
#define NW (NB * 32)
#define LOGIT_NPB 6283          // ceil(50257 / 8) logits blocks
#define FIN_BLOCKS 197          // ceil(VOCAB / 256)

// Scratch (__device__ globals — allocation-free rule)
__device__ float g_partA[8192];   // layer1 partials: [0,4096)=Wih, [4096,8192)=Whh
__device__ float g_partB[8192];   // layer2 partials
__device__ float g_h2[H];
__device__ float2 g_pairs[LOGIT_NPB];
__device__ unsigned g_cnt[4];
__device__ volatile unsigned g_gen[4];

// ---------------------------------------------------------------------------
__device__ __forceinline__ float sigmoidf_fast(float x) {
    return 1.f / (1.f + __expf(-x));
}

__device__ __forceinline__ void merge_pair(float& m, float& s, float m2, float s2) {
    if (m2 > m) { float t = s; s = s2 + t * __expf(m - m2); m = m2; }
    else if (m2 != -INFINITY) { s += s2 * __expf(m2 - m); }
}

// Grid-wide spin barrier (all NB blocks co-resident; gen monotonic across replays)
__device__ __forceinline__ void gsync(int b) {
    __syncthreads();
    if (threadIdx.x == 0) {
        __threadfence();
        unsigned cur = g_gen[b];
        unsigned pos = atomicAdd(&g_cnt[b], 1u);
        if (pos == NB - 1) {
            g_cnt[b] = 0;
            __threadfence();
            g_gen[b] = cur + 1;
        } else {
            while (g_gen[b] == cur) __nanosleep(64);
        }
        __threadfence();
    }
    __syncthreads();
}

// 256-bit loads (LDG.E.256)
struct f8 { float4 a, b; };

__device__ __forceinline__ f8 ld8(const float* p) {
    f8 v;
    asm volatile(
        "{\n\t.reg .b64 q0,q1,q2,q3;\n\t"
        "ld.global.nc.v4.b64 {q0,q1,q2,q3}, [%8];\n\t"
        "mov.b64 {%0,%1}, q0;\n\tmov.b64 {%2,%3}, q1;\n\t"
        "mov.b64 {%4,%5}, q2;\n\tmov.b64 {%6,%7}, q3;\n\t}"
        : "=f"(v.a.x), "=f"(v.a.y), "=f"(v.a.z), "=f"(v.a.w),
          "=f"(v.b.x), "=f"(v.b.y), "=f"(v.b.z), "=f"(v.b.w)
        : "l"(p));
    return v;
}

__device__ __forceinline__ void row_load(const float* W, int lane, f8 w[4]) {
#pragma unroll
    for (int k = 0; k < 4; k++) w[k] = ld8(W + (k * 32 + lane) * 8);
}

__device__ __forceinline__ float dot8(const f8& w, const float4& x0, const float4& x1) {
    return w.a.x * x0.x + w.a.y * x0.y + w.a.z * x0.z + w.a.w * x0.w
         + w.b.x * x1.x + w.b.y * x1.y + w.b.z * x1.z + w.b.w * x1.w;
}

__device__ __forceinline__ float row_dot(const f8 w[4], const float4* v4, int lane) {
    float acc = 0.f;
#pragma unroll
    for (int k = 0; k < 4; k++) {
        int c = (k * 32 + lane) * 2;
        acc += dot8(w[k], v4[c], v4[c + 1]);
    }
    return acc;
}

__device__ __forceinline__ float warp_sum(float acc) {
#pragma unroll
    for (int o = 16; o > 0; o >>= 1) acc += __shfl_down_sync(0xffffffffu, acc, o);
    return acc;
}

// LSTM elementwise for element j (torch gate order i, f, g, o)
__device__ __forceinline__ void act_phase(
        const float* __restrict__ part,
        const float* __restrict__ bih, const float* __restrict__ bhh,
        float cin, float& hout, float& cout, int j) {
    float gi = part[j]         + part[4096 + j]         + bih[j]         + bhh[j];
    float gf = part[j + H]     + part[4096 + j + H]     + bih[j + H]     + bhh[j + H];
    float gg = part[j + 2 * H] + part[4096 + j + 2 * H] + bih[j + 2 * H] + bhh[j + 2 * H];
    float go = part[j + 3 * H] + part[4096 + j + 3 * H] + bih[j + 3 * H] + bhh[j + 3 * H];
    cout = sigmoidf_fast(gf) * cin + sigmoidf_fast(gi) * tanhf(gg);
    hout = sigmoidf_fast(go) * tanhf(cout);
}

// ---------------------------------------------------------------------------
// Gates GEMV phase (inside persistent kernel): 8192 virtual rows, 1 row/step.
// ---------------------------------------------------------------------------
__device__ __forceinline__ void gates_phase(
        const float* __restrict__ Wih, const float* __restrict__ Whh,
        const float4* sx4, const float4* sh4, float* __restrict__ part,
        int gw, int lane, bool xz, bool hz) {
    for (int vr = gw; vr < 8192; vr += NW) {
        bool isA = vr < 4096;
        bool active = isA ? !xz : !hz;
        float acc = 0.f;
        if (active) {
            const float* W = (isA ? Wih : Whh) + (long)(vr & 4095) * H;
            f8 w[4];
            row_load(W, lane, w);
            acc = row_dot(w, isA ? sx4 : sh4, lane);
        }
        acc = warp_sum(acc);
        if (lane == 0) part[vr] = acc;
    }
}

// ---------------------------------------------------------------------------
// Kernel 1 (persistent): embed -> gates1 -> act1 -> gates2 -> act2 -> g_h2.
// ---------------------------------------------------------------------------
__global__ void __launch_bounds__(NT, 1) lstm_kernel(
        const int* __restrict__ id, const float* __restrict__ h0,
        const float* __restrict__ c0, const float* __restrict__ emb,
        const float* __restrict__ Wih, const float* __restrict__ Whh,
        const float* __restrict__ bih, const float* __restrict__ bhh,
        float* __restrict__ out, int write_tail) {
    __shared__ float sx[H];
    __shared__ float sh[H];
    __shared__ int s_nzx, s_nzh;

    int t = threadIdx.x, lane = t & 31, warp = t >> 5, b = blockIdx.x;
    int gw = b * 32 + warp;
    const float4* sx4 = (const float4*)sx;
    const float4* sh4 = (const float4*)sh;

    // P0: stage relu(emb[id]) and h0; detect all-zero source vectors
    if (t == 0) { s_nzx = 0; s_nzh = 0; }
    __syncthreads();
    {
        float xv = fmaxf(emb[(long)id[0] * H + t], 0.f);
        float hv = h0[t];
        sx[t] = xv; sh[t] = hv;
        if (xv != 0.f) s_nzx = 1;
        if (hv != 0.f) s_nzh = 1;
    }
    __syncthreads();

    // P1: layer-1 gates (Whh half skipped when h0 == 0)
    gates_phase(Wih, Whh, sx4, sh4, g_partA, gw, lane, !s_nzx, !s_nzh);
    gsync(0);

    // P2: act1 — redundant per block; c1 stays in a register
    float h1, c1;
    act_phase(g_partA, bih, bhh, c0[t], h1, c1, t);
    __syncthreads();
    if (t == 0) { s_nzx = 0; s_nzh = 0; }
    __syncthreads();
    {
        float xv = fmaxf(h1, 0.f);
        sx[t] = xv; sh[t] = h1;
        if (xv != 0.f) s_nzx = 1;
        if (h1 != 0.f) s_nzh = 1;
    }
    __syncthreads();

    // P3: layer-2 gates (Wih re-read is L2-hot)
    gates_phase(Wih, Whh, sx4, sh4, g_partB, gw, lane, !s_nzx, !s_nzh);
    gsync(1);

    // P4: act2 — block 0 writes g_h2 and the (h, c) tail
    float h2, c2;
    act_phase(g_partB, bih, bhh, c1, h2, c2, t);
    if (b == 0) {
        g_h2[t] = h2;
        if (write_tail) {
            out[VOCAB + t]     = h2;
            out[VOCAB + H + t] = c2;
        }
    }
}

// ---------------------------------------------------------------------------
// Kernel 2: logits GEMV — small blocks (256 thr, 8 warps, 1 row/warp),
// high occupancy + block churn. Emits logits + per-block online pair.
// ---------------------------------------------------------------------------
__global__ void __launch_bounds__(256, 5) logits_kernel(
        const float* __restrict__ Wout, const float* __restrict__ bout,
        float* __restrict__ out) {
    __shared__ float4 shh[H / 4];
    __shared__ float2 wpairs[8];
    int t = threadIdx.x, lane = t & 31, warp = t >> 5;

    const float4* h4 = (const float4*)g_h2;
    for (int i = t; i < H / 4; i += 256) shh[i] = h4[i];
    __syncthreads();

    int row = blockIdx.x * 8 + warp;
    int rc = row < VOCAB ? row : 0;        // clamp: loads always valid
    f8 w[4];
    row_load(Wout + (long)rc * H, lane, w);
    float acc = row_dot(w, shh, lane);
    acc = warp_sum(acc);

    if (lane == 0) {
        float m = -INFINITY, s = 0.f;
        if (row < VOCAB) {
            float v = acc + bout[row];
            out[row] = v;
            m = v; s = 1.0f;
        }
        wpairs[warp] = make_float2(m, s);
    }
    __syncthreads();
    if (t == 0) {
        float mm = wpairs[0].x, ss = wpairs[0].y;
#pragma unroll
        for (int wq = 1; wq < 8; wq++) merge_pair(mm, ss, wpairs[wq].x, wpairs[wq].y);
        g_pairs[blockIdx.x] = make_float2(mm, ss);
    }
}

// ---------------------------------------------------------------------------
// Kernel 3: each block redundantly reduces all pairs (L2-resident, ~50KB) to
// lse (identical order => identical bits), then subtracts from its slice.
// ---------------------------------------------------------------------------
__global__ void __launch_bounds__(256) finish_kernel(float* __restrict__ out) {
    __shared__ float2 red[8];
    __shared__ float s_lse;
    int t = threadIdx.x, lane = t & 31, warp = t >> 5;

    float m = -INFINITY, s = 0.f;
    for (int i = t; i < LOGIT_NPB; i += 256) {
        float2 p = g_pairs[i];
        merge_pair(m, s, p.x, p.y);
    }
#pragma unroll
    for (int o = 16; o > 0; o >>= 1) {
        float m2 = __shfl_down_sync(0xffffffffu, m, o);
        float s2 = __shfl_down_sync(0xffffffffu, s, o);
        merge_pair(m, s, m2, s2);
    }
    if (lane == 0) red[warp] = make_float2(m, s);
    __syncthreads();
    if (t == 0) {
        m = red[0].x; s = red[0].y;
#pragma unroll
        for (int wq = 1; wq < 8; wq++) merge_pair(m, s, red[wq].x, red[wq].y);
        s_lse = m + logf(s);
    }
    __syncthreads();

    int i = blockIdx.x * 256 + t;
    if (i < VOCAB) out[i] -= s_lse;
}

// ---------------------------------------------------------------------------
extern "C" void kernel_launch(void* const* d_in, const int* in_sizes, int n_in,
                              void* d_out, int out_size) {
    const int*   id   = (const int*)d_in[0];
    const float* h0   = (const float*)d_in[1];
    const float* c0   = (const float*)d_in[2];
    const float* emb  = (const float*)d_in[3];
    const float* Wih  = (const float*)d_in[4];
    const float* Whh  = (const float*)d_in[5];
    const float* bih  = (const float*)d_in[6];
    const float* bhh  = (const float*)d_in[7];
    const float* Wout = (const float*)d_in[8];
    const float* bout = (const float*)d_in[9];
    float* out = (float*)d_out;

    int write_tail = (out_size >= VOCAB + 2 * H) ? 1 : 0;

    lstm_kernel<<<NB, NT>>>(id, h0, c0, emb, Wih, Whh, bih, bhh, out, write_tail);
    logits_kernel<<<LOGIT_NPB, 256>>>(Wout, bout, out);
    finish_kernel<<<FIN_BLOCKS, 256>>>(out);
}

// round 14
// speedup vs baseline: 1.1877x; 1.1877x over previous
#include <cuda_runtime.h>
#include <math.h>

#define H 1024
#define VOCAB 50257
#define NB 148                  // blocks == persistent, one per SM (<= SM count)
#define NT 1024
#define NW (NB * 32)            // 4736 warps
#define FIN_CHUNK 340           // ceil(VOCAB / NB)

// Scratch (__device__ globals — allocation-free rule)
__device__ float g_partA[8192];     // layer1 partials: [0,4096)=Wih, [4096,8192)=Whh
__device__ float g_partB[8192];     // layer2 partials
__device__ float2 g_pairs[NB];
__device__ unsigned g_cnt[4];
__device__ volatile unsigned g_gen[4];

// ---------------------------------------------------------------------------
__device__ __forceinline__ float sigmoidf_fast(float x) {
    return 1.f / (1.f + __expf(-x));
}

__device__ __forceinline__ void merge_pair(float& m, float& s, float m2, float s2) {
    if (m2 > m) { float t = s; s = s2 + t * __expf(m - m2); m = m2; }
    else if (m2 != -INFINITY) { s += s2 * __expf(m2 - m); }
}

// Grid-wide spin barrier. Safe because all NB blocks are co-resident.
// gen is monotonic across graph replays; cnt self-resets. Deterministic work.
__device__ __forceinline__ void gsync(int b) {
    __syncthreads();
    if (threadIdx.x == 0) {
        __threadfence();
        unsigned cur = g_gen[b];
        unsigned pos = atomicAdd(&g_cnt[b], 1u);
        if (pos == NB - 1) {
            g_cnt[b] = 0;
            __threadfence();
            g_gen[b] = cur + 1;
        } else {
            while (g_gen[b] == cur) __nanosleep(64);
        }
        __threadfence();
    }
    __syncthreads();
}

// 256-bit loads (LDG.E.256)
struct f8 { float4 a, b; };

__device__ __forceinline__ f8 ld8(const float* p) {
    f8 v;
    asm volatile(
        "{\n\t.reg .b64 q0,q1,q2,q3;\n\t"
        "ld.global.nc.v4.b64 {q0,q1,q2,q3}, [%8];\n\t"
        "mov.b64 {%0,%1}, q0;\n\tmov.b64 {%2,%3}, q1;\n\t"
        "mov.b64 {%4,%5}, q2;\n\tmov.b64 {%6,%7}, q3;\n\t}"
        : "=f"(v.a.x), "=f"(v.a.y), "=f"(v.a.z), "=f"(v.a.w),
          "=f"(v.b.x), "=f"(v.b.y), "=f"(v.b.z), "=f"(v.b.w)
        : "l"(p));
    return v;
}

__device__ __forceinline__ void row_load(const float* W, int lane, f8 w[4]) {
#pragma unroll
    for (int k = 0; k < 4; k++) w[k] = ld8(W + (k * 32 + lane) * 8);
}

__device__ __forceinline__ float dot8(const f8& w, const float4& x0, const float4& x1) {
    return w.a.x * x0.x + w.a.y * x0.y + w.a.z * x0.z + w.a.w * x0.w
         + w.b.x * x1.x + w.b.y * x1.y + w.b.z * x1.z + w.b.w * x1.w;
}

__device__ __forceinline__ float row_dot(const f8 w[4], const float4* v4, int lane) {
    float acc = 0.f;
#pragma unroll
    for (int k = 0; k < 4; k++) {
        int c = (k * 32 + lane) * 2;
        acc += dot8(w[k], v4[c], v4[c + 1]);
    }
    return acc;
}

__device__ __forceinline__ float warp_sum(float acc) {
#pragma unroll
    for (int o = 16; o > 0; o >>= 1) acc += __shfl_down_sync(0xffffffffu, acc, o);
    return acc;
}

// LSTM elementwise for element j (torch gate order i, f, g, o)
__device__ __forceinline__ void act_phase(
        const float* __restrict__ part,
        const float* __restrict__ bih, const float* __restrict__ bhh,
        float cin, float& hout, float& cout, int j) {
    float gi = part[j]         + part[4096 + j]         + bih[j]         + bhh[j];
    float gf = part[j + H]     + part[4096 + j + H]     + bih[j + H]     + bhh[j + H];
    float gg = part[j + 2 * H] + part[4096 + j + 2 * H] + bih[j + 2 * H] + bhh[j + 2 * H];
    float go = part[j + 3 * H] + part[4096 + j + 3 * H] + bih[j + 3 * H] + bhh[j + 3 * H];
    cout = sigmoidf_fast(gf) * cin + sigmoidf_fast(gi) * tanhf(gg);
    hout = sigmoidf_fast(go) * tanhf(cout);
}

// ---------------------------------------------------------------------------
// Gates GEMV phase: 8192 virtual rows over NW warps, 1 row per step.
// vr < 4096: Wih row vs relu'd x (sx).  vr >= 4096: Whh row vs h (sh).
// Zero-source halves: no loads, partial written as 0.
// ---------------------------------------------------------------------------
__device__ __forceinline__ void gates_phase(
        const float* __restrict__ Wih, const float* __restrict__ Whh,
        const float* sx, const float* sh, float* __restrict__ part,
        int gw, int lane, bool xz, bool hz) {
    for (int vr = gw; vr < 8192; vr += NW) {
        bool isA = vr < 4096;
        bool active = isA ? !xz : !hz;
        float acc = 0.f;
        if (active) {
            const float* W = (isA ? Wih : Whh) + (long)(vr & 4095) * H;
            f8 w[4];
            row_load(W, lane, w);
            acc = row_dot(w, (const float4*)(isA ? sx : sh), lane);
        }
        acc = warp_sum(acc);
        if (lane == 0) part[vr] = acc;
    }
}

// ---------------------------------------------------------------------------
// ONE persistent kernel: embed -> gates1 -> act1 -> gates2 -> act2 ->
// logits (+online softmax pairs) -> lse -> subtract. 3 grid barriers.
// ---------------------------------------------------------------------------
__global__ void __launch_bounds__(NT, 1) decoder_kernel(
        const int* __restrict__ id, const float* __restrict__ h0,
        const float* __restrict__ c0, const float* __restrict__ emb,
        const float* __restrict__ Wih, const float* __restrict__ Whh,
        const float* __restrict__ bih, const float* __restrict__ bhh,
        const float* __restrict__ Wout, const float* __restrict__ bout,
        float* __restrict__ out, int write_tail) {
    __shared__ float sx[H];
    __shared__ float sh[H];
    __shared__ float2 spair[32];
    __shared__ float s_lse;
    __shared__ int s_nzx, s_nzh;

    int t = threadIdx.x, lane = t & 31, warp = t >> 5;
    int gw = blockIdx.x * 32 + warp;

    // P0: stage relu(emb[id]) and h0 in smem; detect all-zero source vectors
    if (t == 0) { s_nzx = 0; s_nzh = 0; }
    __syncthreads();
    {
        float xv = fmaxf(emb[(long)id[0] * H + t], 0.f);
        float hv = h0[t];
        sx[t] = xv; sh[t] = hv;
        if (xv != 0.f) s_nzx = 1;
        if (hv != 0.f) s_nzh = 1;
    }
    __syncthreads();

    // P1: layer-1 gates GEMV (Whh half skipped when h0 == 0)
    gates_phase(Wih, Whh, sx, sh, g_partA, gw, lane, !s_nzx, !s_nzh);
    gsync(0);

    // P2: act1 — computed redundantly per block; c1 stays in a register
    float h1, c1;
    act_phase(g_partA, bih, bhh, c0[t], h1, c1, t);
    __syncthreads();
    if (t == 0) { s_nzx = 0; s_nzh = 0; }
    __syncthreads();
    {
        float xv = fmaxf(h1, 0.f);
        sx[t] = xv;
        sh[t] = h1;
        if (xv != 0.f) s_nzx = 1;
        if (h1 != 0.f) s_nzh = 1;
    }
    __syncthreads();

    // P3: layer-2 gates GEMV (same weights per reference)
    gates_phase(Wih, Whh, sx, sh, g_partB, gw, lane, !s_nzx, !s_nzh);
    gsync(1);

    // P4: act2 — redundant per block; block 0 writes the (h, c) tail
    float h2, c2;
    act_phase(g_partB, bih, bhh, c1, h2, c2, t);
    __syncthreads();
    sx[t] = h2;
    if (write_tail && blockIdx.x == 0) {
        out[VOCAB + t]     = h2;
        out[VOCAB + H + t] = c2;
    }
    __syncthreads();

    // P5: logits GEMV + per-warp online (max, sumexp)
    float m = -INFINITY, s = 0.f;
    const float4* h4 = (const float4*)sx;
    for (int row = gw; row < VOCAB; row += NW) {
        const float* p = Wout + (long)row * H;
        f8 w[4];
        row_load(p, lane, w);
        float acc = row_dot(w, h4, lane);
        acc = warp_sum(acc);
        if (lane == 0) {
            float v = acc + bout[row];
            out[row] = v;
            merge_pair(m, s, v, 1.0f);
        }
    }
    if (lane == 0) spair[warp] = make_float2(m, s);
    __syncthreads();
    if (t == 0) {
        float mm = spair[0].x, ss = spair[0].y;
#pragma unroll
        for (int wq = 1; wq < 32; wq++) merge_pair(mm, ss, spair[wq].x, spair[wq].y);
        g_pairs[blockIdx.x] = make_float2(mm, ss);
    }
    gsync(2);

    // P6: every block redundantly reduces g_pairs (identical order => identical
    // bits), then subtracts lse from its slice of out.
    {
        float mm = -INFINITY, ss = 0.f;
        if (t < NB) { float2 p = g_pairs[t]; mm = p.x; ss = p.y; }
#pragma unroll
        for (int o = 16; o > 0; o >>= 1) {
            float m2 = __shfl_down_sync(0xffffffffu, mm, o);
            float s2 = __shfl_down_sync(0xffffffffu, ss, o);
            merge_pair(mm, ss, m2, s2);
        }
        if (lane == 0 && warp < 5) spair[warp] = make_float2(mm, ss);
        __syncthreads();
        if (t == 0) {
            mm = spair[0].x; ss = spair[0].y;
#pragma unroll
            for (int wq = 1; wq < 5; wq++) merge_pair(mm, ss, spair[wq].x, spair[wq].y);
            s_lse = mm + logf(ss);
        }
        __syncthreads();
    }
    int i = blockIdx.x * FIN_CHUNK + t;
    if (t < FIN_CHUNK && i < VOCAB) out[i] -= s_lse;
}

// ---------------------------------------------------------------------------
extern "C" void kernel_launch(void* const* d_in, const int* in_sizes, int n_in,
                              void* d_out, int out_size) {
    const int*   id   = (const int*)d_in[0];
    const float* h0   = (const float*)d_in[1];
    const float* c0   = (const float*)d_in[2];
    const float* emb  = (const float*)d_in[3];
    const float* Wih  = (const float*)d_in[4];
    const float* Whh  = (const float*)d_in[5];
    const float* bih  = (const float*)d_in[6];
    const float* bhh  = (const float*)d_in[7];
    const float* Wout = (const float*)d_in[8];
    const float* bout = (const float*)d_in[9];
    float* out = (float*)d_out;

    int write_tail = (out_size >= VOCAB + 2 * H) ? 1 : 0;

    decoder_kernel<<<NB, NT>>>(id, h0, c0, emb, Wih, Whh, bih, bhh,
                               Wout, bout, out, write_tail);
}

// round 15
// speedup vs baseline: 1.2190x; 1.0264x over previous
#include <cuda_runtime.h>
#include <math.h>

#define H 1024
#define VOCAB 50257
#define NB 148                  // blocks == persistent, one per SM (<= SM count)
#define NT 1024
#define NW (NB * 32)            // 4736 warps
#define FIN_CHUNK 340           // ceil(VOCAB / NB)

// Scratch (__device__ globals — allocation-free rule)
__device__ float g_partA[8192];     // layer1 partials: [0,4096)=Wih, [4096,8192)=Whh
__device__ float g_partB[8192];     // layer2 partials
__device__ float2 g_pairs[NB];
__device__ unsigned g_cnt[4];
__device__ volatile unsigned g_gen[4];

// ---------------------------------------------------------------------------
__device__ __forceinline__ float sigmoidf_fast(float x) {
    return 1.f / (1.f + __expf(-x));
}

__device__ __forceinline__ void merge_pair(float& m, float& s, float m2, float s2) {
    if (m2 > m) { float t = s; s = s2 + t * __expf(m - m2); m = m2; }
    else if (m2 != -INFINITY) { s += s2 * __expf(m2 - m); }
}

// Grid-wide spin barrier. Safe because all NB blocks are co-resident.
// gen is monotonic across graph replays; cnt self-resets. Deterministic work.
__device__ __forceinline__ void gsync(int b) {
    __syncthreads();
    if (threadIdx.x == 0) {
        __threadfence();
        unsigned cur = g_gen[b];
        unsigned pos = atomicAdd(&g_cnt[b], 1u);
        if (pos == NB - 1) {
            g_cnt[b] = 0;
            __threadfence();
            g_gen[b] = cur + 1;
        } else {
            while (g_gen[b] == cur) __nanosleep(64);
        }
        __threadfence();
    }
    __syncthreads();
}

// 256-bit streaming loads, L2-only (.cg bypasses L1 allocation entirely —
// the .nc texture path allocates dead lines and binds on per-SM miss slots)
struct f8 { float4 a, b; };

__device__ __forceinline__ f8 ld8(const float* p) {
    f8 v;
    asm volatile(
        "{\n\t.reg .b64 q0,q1,q2,q3;\n\t"
        "ld.global.cg.v4.b64 {q0,q1,q2,q3}, [%8];\n\t"
        "mov.b64 {%0,%1}, q0;\n\tmov.b64 {%2,%3}, q1;\n\t"
        "mov.b64 {%4,%5}, q2;\n\tmov.b64 {%6,%7}, q3;\n\t}"
        : "=f"(v.a.x), "=f"(v.a.y), "=f"(v.a.z), "=f"(v.a.w),
          "=f"(v.b.x), "=f"(v.b.y), "=f"(v.b.z), "=f"(v.b.w)
        : "l"(p));
    return v;
}

__device__ __forceinline__ void row_load(const float* W, int lane, f8 w[4]) {
#pragma unroll
    for (int k = 0; k < 4; k++) w[k] = ld8(W + (k * 32 + lane) * 8);
}

__device__ __forceinline__ float dot8(const f8& w, const float4& x0, const float4& x1) {
    return w.a.x * x0.x + w.a.y * x0.y + w.a.z * x0.z + w.a.w * x0.w
         + w.b.x * x1.x + w.b.y * x1.y + w.b.z * x1.z + w.b.w * x1.w;
}

__device__ __forceinline__ float row_dot(const f8 w[4], const float4* v4, int lane) {
    float acc = 0.f;
#pragma unroll
    for (int k = 0; k < 4; k++) {
        int c = (k * 32 + lane) * 2;
        acc += dot8(w[k], v4[c], v4[c + 1]);
    }
    return acc;
}

__device__ __forceinline__ float warp_sum(float acc) {
#pragma unroll
    for (int o = 16; o > 0; o >>= 1) acc += __shfl_down_sync(0xffffffffu, acc, o);
    return acc;
}

// LSTM elementwise for element j (torch gate order i, f, g, o)
__device__ __forceinline__ void act_phase(
        const float* __restrict__ part,
        const float* __restrict__ bih, const float* __restrict__ bhh,
        float cin, float& hout, float& cout, int j) {
    float gi = part[j]         + part[4096 + j]         + bih[j]         + bhh[j];
    float gf = part[j + H]     + part[4096 + j + H]     + bih[j + H]     + bhh[j + H];
    float gg = part[j + 2 * H] + part[4096 + j + 2 * H] + bih[j + 2 * H] + bhh[j + 2 * H];
    float go = part[j + 3 * H] + part[4096 + j + 3 * H] + bih[j + 3 * H] + bhh[j + 3 * H];
    cout = sigmoidf_fast(gf) * cin + sigmoidf_fast(gi) * tanhf(gg);
    hout = sigmoidf_fast(go) * tanhf(cout);
}

// ---------------------------------------------------------------------------
// Gates GEMV phase: 8192 virtual rows over NW warps, 1 row per step.
// vr < 4096: Wih row vs relu'd x (sx).  vr >= 4096: Whh row vs h (sh).
// Zero-source halves: no loads, partial written as 0.
// ---------------------------------------------------------------------------
__device__ __forceinline__ void gates_phase(
        const float* __restrict__ Wih, const float* __restrict__ Whh,
        const float* sx, const float* sh, float* __restrict__ part,
        int gw, int lane, bool xz, bool hz) {
    for (int vr = gw; vr < 8192; vr += NW) {
        bool isA = vr < 4096;
        bool active = isA ? !xz : !hz;
        float acc = 0.f;
        if (active) {
            const float* W = (isA ? Wih : Whh) + (long)(vr & 4095) * H;
            f8 w[4];
            row_load(W, lane, w);
            acc = row_dot(w, (const float4*)(isA ? sx : sh), lane);
        }
        acc = warp_sum(acc);
        if (lane == 0) part[vr] = acc;
    }
}

// ---------------------------------------------------------------------------
// ONE persistent kernel: embed -> gates1 -> act1 -> gates2 -> act2 ->
// logits (+online softmax pairs) -> lse -> subtract. 3 grid barriers.
// ---------------------------------------------------------------------------
__global__ void __launch_bounds__(NT, 1) decoder_kernel(
        const int* __restrict__ id, const float* __restrict__ h0,
        const float* __restrict__ c0, const float* __restrict__ emb,
        const float* __restrict__ Wih, const float* __restrict__ Whh,
        const float* __restrict__ bih, const float* __restrict__ bhh,
        const float* __restrict__ Wout, const float* __restrict__ bout,
        float* __restrict__ out, int write_tail) {
    __shared__ float sx[H];
    __shared__ float sh[H];
    __shared__ float2 spair[32];
    __shared__ float s_lse;
    __shared__ int s_nzx, s_nzh;

    int t = threadIdx.x, lane = t & 31, warp = t >> 5;
    int gw = blockIdx.x * 32 + warp;

    // P0: stage relu(emb[id]) and h0 in smem; detect all-zero source vectors
    if (t == 0) { s_nzx = 0; s_nzh = 0; }
    __syncthreads();
    {
        float xv = fmaxf(emb[(long)id[0] * H + t], 0.f);
        float hv = h0[t];
        sx[t] = xv; sh[t] = hv;
        if (xv != 0.f) s_nzx = 1;
        if (hv != 0.f) s_nzh = 1;
    }
    __syncthreads();

    // P1: layer-1 gates GEMV (Whh half skipped when h0 == 0)
    gates_phase(Wih, Whh, sx, sh, g_partA, gw, lane, !s_nzx, !s_nzh);
    gsync(0);

    // P2: act1 — computed redundantly per block; c1 stays in a register
    float h1, c1;
    act_phase(g_partA, bih, bhh, c0[t], h1, c1, t);
    __syncthreads();
    if (t == 0) { s_nzx = 0; s_nzh = 0; }
    __syncthreads();
    {
        float xv = fmaxf(h1, 0.f);
        sx[t] = xv;
        sh[t] = h1;
        if (xv != 0.f) s_nzx = 1;
        if (h1 != 0.f) s_nzh = 1;
    }
    __syncthreads();

    // P3: layer-2 gates GEMV (same weights per reference)
    gates_phase(Wih, Whh, sx, sh, g_partB, gw, lane, !s_nzx, !s_nzh);
    gsync(1);

    // P4: act2 — redundant per block; block 0 writes the (h, c) tail
    float h2, c2;
    act_phase(g_partB, bih, bhh, c1, h2, c2, t);
    __syncthreads();
    sx[t] = h2;
    if (write_tail && blockIdx.x == 0) {
        out[VOCAB + t]     = h2;
        out[VOCAB + H + t] = c2;
    }
    __syncthreads();

    // P5: logits GEMV + per-warp online (max, sumexp)
    float m = -INFINITY, s = 0.f;
    const float4* h4 = (const float4*)sx;
    for (int row = gw; row < VOCAB; row += NW) {
        const float* p = Wout + (long)row * H;
        f8 w[4];
        row_load(p, lane, w);
        float acc = row_dot(w, h4, lane);
        acc = warp_sum(acc);
        if (lane == 0) {
            float v = acc + bout[row];
            out[row] = v;
            merge_pair(m, s, v, 1.0f);
        }
    }
    if (lane == 0) spair[warp] = make_float2(m, s);
    __syncthreads();
    if (t == 0) {
        float mm = spair[0].x, ss = spair[0].y;
#pragma unroll
        for (int wq = 1; wq < 32; wq++) merge_pair(mm, ss, spair[wq].x, spair[wq].y);
        g_pairs[blockIdx.x] = make_float2(mm, ss);
    }
    gsync(2);

    // P6: every block redundantly reduces g_pairs (identical order => identical
    // bits), then subtracts lse from its slice of out.
    {
        float mm = -INFINITY, ss = 0.f;
        if (t < NB) { float2 p = g_pairs[t]; mm = p.x; ss = p.y; }
#pragma unroll
        for (int o = 16; o > 0; o >>= 1) {
            float m2 = __shfl_down_sync(0xffffffffu, mm, o);
            float s2 = __shfl_down_sync(0xffffffffu, ss, o);
            merge_pair(mm, ss, m2, s2);
        }
        if (lane == 0 && warp < 5) spair[warp] = make_float2(mm, ss);
        __syncthreads();
        if (t == 0) {
            mm = spair[0].x; ss = spair[0].y;
#pragma unroll
            for (int wq = 1; wq < 5; wq++) merge_pair(mm, ss, spair[wq].x, spair[wq].y);
            s_lse = mm + logf(ss);
        }
        __syncthreads();
    }
    int i = blockIdx.x * FIN_CHUNK + t;
    if (t < FIN_CHUNK && i < VOCAB) out[i] -= s_lse;
}

// ---------------------------------------------------------------------------
extern "C" void kernel_launch(void* const* d_in, const int* in_sizes, int n_in,
                              void* d_out, int out_size) {
    const int*   id   = (const int*)d_in[0];
    const float* h0   = (const float*)d_in[1];
    const float* c0   = (const float*)d_in[2];
    const float* emb  = (const float*)d_in[3];
    const float* Wih  = (const float*)d_in[4];
    const float* Whh  = (const float*)d_in[5];
    const float* bih  = (const float*)d_in[6];
    const float* bhh  = (const float*)d_in[7];
    const float* Wout = (const float*)d_in[8];
    const float* bout = (const float*)d_in[9];
    float* out = (float*)d_out;

    int write_tail = (out_size >= VOCAB + 2 * H) ? 1 : 0;

    decoder_kernel<<<NB, NT>>>(id, h0, c0, emb, Wih, Whh, bih, bhh,
                               Wout, bout, out, write_tail);
}